// round 10
// baseline (speedup 1.0000x reference)
#include <cuda_runtime.h>
#include <cstdint>

#define WARPS_PB  4
#define THREADS   (WARPS_PB * 32)
#define STAGES    3
#define NBLOCKS   740          // 148 SMs x 5 CTAs (smem-limited)

__device__ __forceinline__ void cp16(uint32_t smem_dst, const void* gmem_src) {
    asm volatile("cp.async.ca.shared.global [%0], [%1], 16;"
                 :: "r"(smem_dst), "l"(gmem_src) : "memory");
}
__device__ __forceinline__ void cp_commit() {
    asm volatile("cp.async.commit_group;" ::: "memory");
}
__device__ __forceinline__ void cp_wait2() {
    asm volatile("cp.async.wait_group 2;" ::: "memory");
}

// smem ring: per warp, STAGES stages of 7 rows x 32 float4 (512 B each).
// rows: 0=v(bases[pr]) 1=h 2=t 3=r(vvrel[pr]) 4=nh 5=nt 6=nr(vvrel[nr])
__global__ __launch_bounds__(THREADS)
void transh_score_cpasync_kernel(
    const int* __restrict__ pos_h, const int* __restrict__ pos_t, const int* __restrict__ pos_r,
    const int* __restrict__ neg_h, const int* __restrict__ neg_t, const int* __restrict__ neg_r,
    const float4* __restrict__ ent,    // [ENT, 32] float4
    const float4* __restrict__ vvrel,  // [ENT, 32] float4
    const float4* __restrict__ bases,  // [REL, 32] float4 (rows are L2-normalized)
    float* __restrict__ out, int n)
{
    __shared__ float4 buf[WARPS_PB][STAGES][7][32];

    const int wl   = threadIdx.x >> 5;        // warp within block
    const int lane = threadIdx.x & 31;
    const int w    = (blockIdx.x * THREADS + threadIdx.x) >> 5;  // global warp
    const int S    = (NBLOCKS * THREADS) >> 5;                   // warp stride

    // smem byte address of this lane's slot in (stage s, row rw)
    const uint32_t base_sa =
        (uint32_t)__cvta_generic_to_shared(&buf[wl][0][0][lane]);
    const uint32_t stage_bytes = 7 * 32 * 16;   // 3584
    const uint32_t row_bytes   = 32 * 16;       // 512

    // Issue the 7 row-copies for triple t into stage s; always commit a group.
    auto issue = [&](int t, int s) {
        if (t < n) {
            const int ir = __ldg(pos_r + t);
            const int ih = __ldg(pos_h + t);
            const int it = __ldg(pos_t + t);
            const int jh = __ldg(neg_h + t);
            const int jt = __ldg(neg_t + t);
            const int jr = __ldg(neg_r + t);
            const uint32_t sa = base_sa + (uint32_t)s * stage_bytes;
            cp16(sa + 0 * row_bytes, bases + (size_t)ir * 32 + lane);
            cp16(sa + 1 * row_bytes, ent   + (size_t)ih * 32 + lane);
            cp16(sa + 2 * row_bytes, ent   + (size_t)it * 32 + lane);
            cp16(sa + 3 * row_bytes, vvrel + (size_t)ir * 32 + lane);
            cp16(sa + 4 * row_bytes, ent   + (size_t)jh * 32 + lane);
            cp16(sa + 5 * row_bytes, ent   + (size_t)jt * 32 + lane);
            cp16(sa + 6 * row_bytes, vvrel + (size_t)jr * 32 + lane);
        }
        cp_commit();
    };

    // Prologue: two stages in flight.
    issue(w,     0);
    issue(w + S, 1);

    int k = 0;
    for (int i = w; i < n; i += S, ++k) {
        // Keep the pipe full: triple i+2S into the stage consumed last iter.
        issue(i + 2 * S, (k + 2) % STAGES);

        // Retire the oldest group (stage k%STAGES); <=2 groups stay pending.
        cp_wait2();

        const int cur = k % STAGES;
        const float4 v  = buf[wl][cur][0][lane];
        const float4 h  = buf[wl][cur][1][lane];
        const float4 t  = buf[wl][cur][2][lane];
        const float4 r  = buf[wl][cur][3][lane];
        const float4 nh = buf[wl][cur][4][lane];
        const float4 nt = buf[wl][cur][5][lane];
        const float4 nr = buf[wl][cur][6][lane];

        // Projection linearity (shared v): sum|P(h)+P(r)-P(t)| = sum|P(h+r-t)|.
        // bases rows are unit-norm -> v.v = 1: skip that reduction + divide.
        float4 dp, dn;
        dp.x = h.x + r.x - t.x;      dp.y = h.y + r.y - t.y;
        dp.z = h.z + r.z - t.z;      dp.w = h.w + r.w - t.w;
        dn.x = nh.x + nr.x - nt.x;   dn.y = nh.y + nr.y - nt.y;
        dn.z = nh.z + nr.z - nt.z;   dn.w = nh.w + nr.w - nt.w;

        float pvp = v.x * dp.x + v.y * dp.y + v.z * dp.z + v.w * dp.w;
        float pvn = v.x * dn.x + v.y * dn.y + v.z * dn.z + v.w * dn.w;
        #pragma unroll
        for (int o = 16; o > 0; o >>= 1) {
            pvp += __shfl_xor_sync(0xFFFFFFFFu, pvp, o);
            pvn += __shfl_xor_sync(0xFFFFFFFFu, pvn, o);
        }
        const float cp = pvp;
        const float cn = pvn;

        float sp = fabsf(dp.x - cp * v.x) + fabsf(dp.y - cp * v.y)
                 + fabsf(dp.z - cp * v.z) + fabsf(dp.w - cp * v.w);
        float sn = fabsf(dn.x - cn * v.x) + fabsf(dn.y - cn * v.y)
                 + fabsf(dn.z - cn * v.z) + fabsf(dn.w - cn * v.w);
        #pragma unroll
        for (int o = 16; o > 0; o >>= 1) {
            sp += __shfl_xor_sync(0xFFFFFFFFu, sp, o);
            sn += __shfl_xor_sync(0xFFFFFFFFu, sn, o);
        }

        if (lane == 0) {
            out[i]     = sp;
            out[n + i] = sn;
        }
    }
}

extern "C" void kernel_launch(void* const* d_in, const int* in_sizes, int n_in,
                              void* d_out, int out_size)
{
    const int*    pos_h = (const int*)d_in[0];
    const int*    pos_t = (const int*)d_in[1];
    const int*    pos_r = (const int*)d_in[2];
    const int*    neg_h = (const int*)d_in[3];
    const int*    neg_t = (const int*)d_in[4];
    const int*    neg_r = (const int*)d_in[5];
    const float4* ent   = (const float4*)d_in[6];
    const float4* vvrel = (const float4*)d_in[7];
    const float4* bases = (const float4*)d_in[8];
    float* out = (float*)d_out;

    const int n = in_sizes[0];  // 65536 triples
    transh_score_cpasync_kernel<<<NBLOCKS, THREADS>>>(
        pos_h, pos_t, pos_r, neg_h, neg_t, neg_r, ent, vvrel, bases, out, n);
}

// round 12
// speedup vs baseline: 1.5118x; 1.5118x over previous
#include <cuda_runtime.h>

#define THREADS 256

__device__ __forceinline__ float4 ld4(const float4* p) { return __ldg(p); }

// One warp handles TWO triples (2w, 2w+1): 14 LDG.128 in flight per thread,
// reduction-tree tail amortized across both. bases rows are L2-normalized
// (v.v == 1), and the hyperplane projector is linear with a shared v:
//   sum|P(h)+P(r)-P(t)| = sum|P(h+r-t)|,  c = v.(h+r-t).
__global__ __launch_bounds__(THREADS)
void transh_score_x2_kernel(
    const int* __restrict__ pos_h, const int* __restrict__ pos_t, const int* __restrict__ pos_r,
    const int* __restrict__ neg_h, const int* __restrict__ neg_t, const int* __restrict__ neg_r,
    const float4* __restrict__ ent,    // [ENT, 32] float4
    const float4* __restrict__ vvrel,  // [ENT, 32] float4
    const float4* __restrict__ bases,  // [REL, 32] float4
    float* __restrict__ out, int n)
{
    const int warp = (blockIdx.x * blockDim.x + threadIdx.x) >> 5;
    const int lane = threadIdx.x & 31;
    const int iA   = 2 * warp;
    const int iB   = 2 * warp + 1;
    if (iA >= n) return;
    const bool hasB = (iB < n);
    const int iBc = hasB ? iB : iA;

    // ---- indices for both triples ----
    const int aph = __ldg(pos_h + iA), bph = __ldg(pos_h + iBc);
    const int apt = __ldg(pos_t + iA), bpt = __ldg(pos_t + iBc);
    const int apr = __ldg(pos_r + iA), bpr = __ldg(pos_r + iBc);
    const int anh = __ldg(neg_h + iA), bnh = __ldg(neg_h + iBc);
    const int ant = __ldg(neg_t + iA), bnt = __ldg(neg_t + iBc);
    const int anr = __ldg(neg_r + iA), bnr = __ldg(neg_r + iBc);

    // ---- 14 row gathers, all independent, issued back-to-back ----
    const float4 vA  = ld4(bases + (size_t)apr * 32 + lane);
    const float4 hA  = ld4(ent   + (size_t)aph * 32 + lane);
    const float4 tA  = ld4(ent   + (size_t)apt * 32 + lane);
    const float4 rA  = ld4(vvrel + (size_t)apr * 32 + lane);
    const float4 nhA = ld4(ent   + (size_t)anh * 32 + lane);
    const float4 ntA = ld4(ent   + (size_t)ant * 32 + lane);
    const float4 nrA = ld4(vvrel + (size_t)anr * 32 + lane);
    const float4 vB  = ld4(bases + (size_t)bpr * 32 + lane);
    const float4 hB  = ld4(ent   + (size_t)bph * 32 + lane);
    const float4 tB  = ld4(ent   + (size_t)bpt * 32 + lane);
    const float4 rB  = ld4(vvrel + (size_t)bpr * 32 + lane);
    const float4 nhB = ld4(ent   + (size_t)bnh * 32 + lane);
    const float4 ntB = ld4(ent   + (size_t)bnt * 32 + lane);
    const float4 nrB = ld4(vvrel + (size_t)bnr * 32 + lane);

    // ---- differences ----
    float4 dpA, dnA, dpB, dnB;
    dpA.x = hA.x + rA.x - tA.x;    dpA.y = hA.y + rA.y - tA.y;
    dpA.z = hA.z + rA.z - tA.z;    dpA.w = hA.w + rA.w - tA.w;
    dnA.x = nhA.x + nrA.x - ntA.x; dnA.y = nhA.y + nrA.y - ntA.y;
    dnA.z = nhA.z + nrA.z - ntA.z; dnA.w = nhA.w + nrA.w - ntA.w;
    dpB.x = hB.x + rB.x - tB.x;    dpB.y = hB.y + rB.y - tB.y;
    dpB.z = hB.z + rB.z - tB.z;    dpB.w = hB.w + rB.w - tB.w;
    dnB.x = nhB.x + nrB.x - ntB.x; dnB.y = nhB.y + nrB.y - ntB.y;
    dnB.z = nhB.z + nrB.z - ntB.z; dnB.w = nhB.w + nrB.w - ntB.w;

    // ---- stage 1: four dot-products, chains interleaved in one tree pass ----
    float cpA = vA.x * dpA.x + vA.y * dpA.y + vA.z * dpA.z + vA.w * dpA.w;
    float cnA = vA.x * dnA.x + vA.y * dnA.y + vA.z * dnA.z + vA.w * dnA.w;
    float cpB = vB.x * dpB.x + vB.y * dpB.y + vB.z * dpB.z + vB.w * dpB.w;
    float cnB = vB.x * dnB.x + vB.y * dnB.y + vB.z * dnB.z + vB.w * dnB.w;
    #pragma unroll
    for (int o = 16; o > 0; o >>= 1) {
        cpA += __shfl_xor_sync(0xFFFFFFFFu, cpA, o);
        cnA += __shfl_xor_sync(0xFFFFFFFFu, cnA, o);
        cpB += __shfl_xor_sync(0xFFFFFFFFu, cpB, o);
        cnB += __shfl_xor_sync(0xFFFFFFFFu, cnB, o);
    }

    // ---- stage 2: four L1-norms, interleaved ----
    float spA = fabsf(dpA.x - cpA * vA.x) + fabsf(dpA.y - cpA * vA.y)
              + fabsf(dpA.z - cpA * vA.z) + fabsf(dpA.w - cpA * vA.w);
    float snA = fabsf(dnA.x - cnA * vA.x) + fabsf(dnA.y - cnA * vA.y)
              + fabsf(dnA.z - cnA * vA.z) + fabsf(dnA.w - cnA * vA.w);
    float spB = fabsf(dpB.x - cpB * vB.x) + fabsf(dpB.y - cpB * vB.y)
              + fabsf(dpB.z - cpB * vB.z) + fabsf(dpB.w - cpB * vB.w);
    float snB = fabsf(dnB.x - cnB * vB.x) + fabsf(dnB.y - cnB * vB.y)
              + fabsf(dnB.z - cnB * vB.z) + fabsf(dnB.w - cnB * vB.w);
    #pragma unroll
    for (int o = 16; o > 0; o >>= 1) {
        spA += __shfl_xor_sync(0xFFFFFFFFu, spA, o);
        snA += __shfl_xor_sync(0xFFFFFFFFu, snA, o);
        spB += __shfl_xor_sync(0xFFFFFFFFu, spB, o);
        snB += __shfl_xor_sync(0xFFFFFFFFu, snB, o);
    }

    if (lane == 0) {
        out[iA]     = spA;
        out[n + iA] = snA;
        if (hasB) {
            out[iB]     = spB;
            out[n + iB] = snB;
        }
    }
}

extern "C" void kernel_launch(void* const* d_in, const int* in_sizes, int n_in,
                              void* d_out, int out_size)
{
    const int*    pos_h = (const int*)d_in[0];
    const int*    pos_t = (const int*)d_in[1];
    const int*    pos_r = (const int*)d_in[2];
    const int*    neg_h = (const int*)d_in[3];
    const int*    neg_t = (const int*)d_in[4];
    const int*    neg_r = (const int*)d_in[5];
    const float4* ent   = (const float4*)d_in[6];
    const float4* vvrel = (const float4*)d_in[7];
    const float4* bases = (const float4*)d_in[8];
    float* out = (float*)d_out;

    const int n = in_sizes[0];  // 65536 triples
    const int nwarps = (n + 1) / 2;
    const int warps_per_block = THREADS / 32;
    const int blocks = (nwarps + warps_per_block - 1) / warps_per_block;
    transh_score_x2_kernel<<<blocks, THREADS>>>(
        pos_h, pos_t, pos_r, neg_h, neg_t, neg_r, ent, vvrel, bases, out, n);
}